// round 3
// baseline (speedup 1.0000x reference)
#include <cuda_runtime.h>
#include <cuda_bf16.h>

// binnings: out[b,g,h,w] = sum_n x[b, IDX[g,n], h, w] * groupn[g,n]
//   x: (8, 64, 512, 512) fp32, groupn: (16, 4) fp32, out: (8, 16, 512, 512)
//   IDX[g,n] = (g/4)*16 + n*4 + (g%4)
//
// HBM-bound, minimal traffic (640 MiB). R3: persistent grid-stride kernel
// (1184 CTAs = 148 SMs x 8) to remove ~13 wave transitions + tail skew.

static constexpr int B = 8;
static constexpr int C = 64;
static constexpr int G = 16;
static constexpr int HW = 512 * 512;
static constexpr int HW4 = HW / 4;             // 65536 float4s per plane
static constexpr int V = 2;                    // float4s per thread per tile
static constexpr int TPB = 256;
static constexpr int TILE_F4 = TPB * V;        // 512 float4s per tile
static constexpr int TILES_PER_PLANE = HW4 / TILE_F4;   // 128
static constexpr int NUM_TILES = TILES_PER_PLANE * G * B;  // 16384
static constexpr int NUM_CTAS = 148 * 8;       // one full resident wave

__global__ __launch_bounds__(TPB)
void binnings_kernel(const float4* __restrict__ x,
                     const float* __restrict__ groupn,
                     float4* __restrict__ out)
{
    const int tid = threadIdx.x;

    for (int tile = blockIdx.x; tile < NUM_TILES; tile += NUM_CTAS) {
        // decompose: tile = ((b*G + g) * TILES_PER_PLANE) + tx
        const int tx = tile & (TILES_PER_PLANE - 1);        // 0..127
        const int bg = tile >> 7;                            // 0..127
        const int g  = bg & (G - 1);
        const int b  = bg >> 4;

        const int ch_base = (g >> 2) * 16 + (g & 3);

        const float w0 = __ldg(&groupn[g * 4 + 0]);
        const float w1 = __ldg(&groupn[g * 4 + 1]);
        const float w2 = __ldg(&groupn[g * 4 + 2]);
        const float w3 = __ldg(&groupn[g * 4 + 3]);

        const long long in_base  = (long long)(b * C + ch_base) * HW4
                                 + tx * TILE_F4 + tid;
        const long long out_base = (long long)(b * G + g) * HW4
                                 + tx * TILE_F4 + tid;

        float4 a0[V], a1[V], a2[V], a3[V];

        #pragma unroll
        for (int v = 0; v < V; v++) {
            const long long p = in_base + v * TPB;
            a0[v] = __ldg(&x[p + 0LL * 4 * HW4]);
            a1[v] = __ldg(&x[p + 1LL * 4 * HW4]);
            a2[v] = __ldg(&x[p + 2LL * 4 * HW4]);
            a3[v] = __ldg(&x[p + 3LL * 4 * HW4]);
        }

        #pragma unroll
        for (int v = 0; v < V; v++) {
            float4 r;
            r.x = fmaf(a0[v].x, w0, fmaf(a1[v].x, w1, fmaf(a2[v].x, w2, a3[v].x * w3)));
            r.y = fmaf(a0[v].y, w0, fmaf(a1[v].y, w1, fmaf(a2[v].y, w2, a3[v].y * w3)));
            r.z = fmaf(a0[v].z, w0, fmaf(a1[v].z, w1, fmaf(a2[v].z, w2, a3[v].z * w3)));
            r.w = fmaf(a0[v].w, w0, fmaf(a1[v].w, w1, fmaf(a2[v].w, w2, a3[v].w * w3)));
            __stcs(&out[out_base + v * TPB], r);
        }
    }
}

extern "C" void kernel_launch(void* const* d_in, const int* in_sizes, int n_in,
                              void* d_out, int out_size)
{
    const float4* x      = (const float4*)d_in[0];
    const float*  groupn = (const float*)d_in[1];
    float4*       out    = (float4*)d_out;

    binnings_kernel<<<NUM_CTAS, TPB>>>(x, groupn, out);
}

// round 4
// speedup vs baseline: 1.0276x; 1.0276x over previous
#include <cuda_runtime.h>
#include <cuda_bf16.h>

// binnings: out[b,g,h,w] = sum_n x[b, IDX[g,n], h, w] * groupn[g,n]
//   x: (8, 64, 512, 512) fp32, groupn: (16, 4) fp32, out: (8, 16, 512, 512)
//   IDX[g,n] = (g/4)*16 + n*4 + (g%4)
//
// HBM-bound, minimal traffic (640 MiB). R4: revert to the R1 shape
// (one float4 per thread, 32768 CTAs — HW oversubscription beats
// software persistence, measured in R3). Cache policy: evict-first
// reads (__ldcs, zero reuse) + default write-back stores so dirty
// output lines linger in the 126MB L2 and writebacks batch lazily.

static constexpr int B = 8;
static constexpr int C = 64;
static constexpr int G = 16;
static constexpr int HW = 512 * 512;
static constexpr int HW4 = HW / 4;            // 65536 float4s per plane

__global__ __launch_bounds__(256)
void binnings_kernel(const float4* __restrict__ x,
                     const float* __restrict__ groupn,
                     float4* __restrict__ out)
{
    const int g = blockIdx.y;      // 0..15
    const int b = blockIdx.z;      // 0..7
    const int p = blockIdx.x * blockDim.x + threadIdx.x;   // float4 index in plane

    const int ch_base = (g >> 2) * 16 + (g & 3);

    const float w0 = __ldg(&groupn[g * 4 + 0]);
    const float w1 = __ldg(&groupn[g * 4 + 1]);
    const float w2 = __ldg(&groupn[g * 4 + 2]);
    const float w3 = __ldg(&groupn[g * 4 + 3]);

    const long long base = (long long)(b * C + ch_base) * HW4 + p;

    const float4 a0 = __ldcs(&x[base + 0LL * 4 * HW4]);
    const float4 a1 = __ldcs(&x[base + 1LL * 4 * HW4]);
    const float4 a2 = __ldcs(&x[base + 2LL * 4 * HW4]);
    const float4 a3 = __ldcs(&x[base + 3LL * 4 * HW4]);

    float4 r;
    r.x = fmaf(a0.x, w0, fmaf(a1.x, w1, fmaf(a2.x, w2, a3.x * w3)));
    r.y = fmaf(a0.y, w0, fmaf(a1.y, w1, fmaf(a2.y, w2, a3.y * w3)));
    r.z = fmaf(a0.z, w0, fmaf(a1.z, w1, fmaf(a2.z, w2, a3.z * w3)));
    r.w = fmaf(a0.w, w0, fmaf(a1.w, w1, fmaf(a2.w, w2, a3.w * w3)));

    out[(long long)(b * G + g) * HW4 + p] = r;
}

extern "C" void kernel_launch(void* const* d_in, const int* in_sizes, int n_in,
                              void* d_out, int out_size)
{
    const float4* x      = (const float4*)d_in[0];
    const float*  groupn = (const float*)d_in[1];
    float4*       out    = (float4*)d_out;

    dim3 block(256);
    dim3 grid(HW4 / 256, G, B);   // 256 x 16 x 8 = 32768 blocks
    binnings_kernel<<<grid, block>>>(x, groupn, out);
}

// round 5
// speedup vs baseline: 1.0498x; 1.0216x over previous
#include <cuda_runtime.h>
#include <cuda_bf16.h>

// binnings: out[b,g,h,w] = sum_n x[b, IDX[g,n], h, w] * groupn[g,n]
//   x: (8, 64, 512, 512) fp32, groupn: (16, 4) fp32, out: (8, 16, 512, 512)
//   IDX[g,n] = (g/4)*16 + n*4 + (g%4)
//
// HBM-bound, minimal traffic (640 MiB). R5: R1 shape (one float4/thread,
// 32768 CTAs, default-cached reads) + WRITE-THROUGH stores (__stwt).
// Rationale: in the harness's back-to-back graph replays, write-back
// stores leave 128 MiB dirty in L2 that collides with the next replay's
// read stream (R4 evidence: ncu kernel 88us but steady-state 98us).
// Write-through streams output to DRAM within its own replay.

static constexpr int B = 8;
static constexpr int C = 64;
static constexpr int G = 16;
static constexpr int HW = 512 * 512;
static constexpr int HW4 = HW / 4;            // 65536 float4s per plane

__global__ __launch_bounds__(256)
void binnings_kernel(const float4* __restrict__ x,
                     const float* __restrict__ groupn,
                     float4* __restrict__ out)
{
    const int g = blockIdx.y;      // 0..15
    const int b = blockIdx.z;      // 0..7
    const int p = blockIdx.x * blockDim.x + threadIdx.x;   // float4 index in plane

    const int ch_base = (g >> 2) * 16 + (g & 3);

    const float w0 = __ldg(&groupn[g * 4 + 0]);
    const float w1 = __ldg(&groupn[g * 4 + 1]);
    const float w2 = __ldg(&groupn[g * 4 + 2]);
    const float w3 = __ldg(&groupn[g * 4 + 3]);

    const long long base = (long long)(b * C + ch_base) * HW4 + p;

    const float4 a0 = __ldg(&x[base + 0LL * 4 * HW4]);
    const float4 a1 = __ldg(&x[base + 1LL * 4 * HW4]);
    const float4 a2 = __ldg(&x[base + 2LL * 4 * HW4]);
    const float4 a3 = __ldg(&x[base + 3LL * 4 * HW4]);

    float4 r;
    r.x = fmaf(a0.x, w0, fmaf(a1.x, w1, fmaf(a2.x, w2, a3.x * w3)));
    r.y = fmaf(a0.y, w0, fmaf(a1.y, w1, fmaf(a2.y, w2, a3.y * w3)));
    r.z = fmaf(a0.z, w0, fmaf(a1.z, w1, fmaf(a2.z, w2, a3.z * w3)));
    r.w = fmaf(a0.w, w0, fmaf(a1.w, w1, fmaf(a2.w, w2, a3.w * w3)));

    __stwt(&out[(long long)(b * G + g) * HW4 + p], r);
}

extern "C" void kernel_launch(void* const* d_in, const int* in_sizes, int n_in,
                              void* d_out, int out_size)
{
    const float4* x      = (const float4*)d_in[0];
    const float*  groupn = (const float*)d_in[1];
    float4*       out    = (float4*)d_out;

    dim3 block(256);
    dim3 grid(HW4 / 256, G, B);   // 256 x 16 x 8 = 32768 blocks
    binnings_kernel<<<grid, block>>>(x, groupn, out);
}